// round 3
// baseline (speedup 1.0000x reference)
#include <cuda_runtime.h>
#include <cstdint>
#include <cstddef>

// Problem constants
#define CB    8
#define CIN   64
#define COUT  64
#define TDIM  512
#define FDIM  161

// Tiling
constexpr int TT  = 64;           // t-tile per block
constexpr int IC  = 8;            // CIN chunk
constexpr int NCH = CIN / IC;     // 8 chunks

// SMEM layout (floats)
constexpr int WS_BLK = 776;                 // 64*12 + 8 pad per (i,fl) block
constexpr int WS_BUF = IC * 2 * WS_BLK;     // 12416
constexpr int XS_ROW = 68;                  // 66 used + 2 pad
constexpr int XS_BUF = IC * 4 * XS_ROW;     // 2176
constexpr int SMEM_FLOATS = 2 * WS_BUF + 2 * XS_BUF;  // 116736 B

// Transformed weights: wT[f][i][o][12]  (k=0..8 valid, 9..11 zero)
constexpr size_t WT_ELEMS = (size_t)FDIM * CIN * COUT * 12;
__device__ float g_wT[WT_ELEMS];

// ---------------------------------------------------------------------------
// Packed f32x2 helpers (sm_100+)
// ---------------------------------------------------------------------------
__device__ __forceinline__ uint64_t pack2(float lo, float hi)
{
    uint64_t r;
    asm("mov.b64 %0, {%1, %2};" : "=l"(r) : "f"(lo), "f"(hi));
    return r;
}
__device__ __forceinline__ void unpack2(float& lo, float& hi, uint64_t v)
{
    asm("mov.b64 {%0, %1}, %2;" : "=f"(lo), "=f"(hi) : "l"(v));
}
__device__ __forceinline__ void ffma2(uint64_t& d, uint64_t a, uint64_t b)
{
    asm("fma.rn.f32x2 %0, %1, %2, %0;" : "+l"(d) : "l"(a), "l"(b));
}

// ---------------------------------------------------------------------------
// Weight transform: kernel[o][i][f][3][3] -> wT[f][i][o][12]
// ---------------------------------------------------------------------------
__global__ void wtrans_kernel(const float* __restrict__ w)
{
    int idx = blockIdx.x * 256 + threadIdx.x;        // over F*CIN*COUT, o fastest
    int total = FDIM * CIN * COUT;
    if (idx >= total) return;
    int o = idx & 63;
    int r = idx >> 6;
    int i = r & 63;
    int f = r >> 6;
    const float* src = w + (((size_t)o * CIN + i) * FDIM + f) * 9;
    float* dst = g_wT + (size_t)idx * 12;
#pragma unroll
    for (int k = 0; k < 9; k++) dst[k] = src[k];
    dst[9] = 0.f; dst[10] = 0.f; dst[11] = 0.f;
}

// ---------------------------------------------------------------------------
// cp.async helpers
// ---------------------------------------------------------------------------
__device__ __forceinline__ void cp_async16(uint32_t s, const void* g)
{
    asm volatile("cp.async.ca.shared.global [%0], [%1], 16;\n" :: "r"(s), "l"(g));
}
__device__ __forceinline__ void cp_async4z(uint32_t s, const void* g, bool ok)
{
    int sz = ok ? 4 : 0;
    asm volatile("cp.async.ca.shared.global [%0], [%1], 4, %2;\n" :: "r"(s), "l"(g), "r"(sz));
}

// ---------------------------------------------------------------------------
// Main conv kernel
//   block: 256 threads -> out[b, 0:64, t0:t0+64, f0:f0+2]
//   thread (og,tg,fl): o = og*4+0..3, t = t0+tg*8+0..7, f = f0+fl
//   accumulators packed f32x2 over output-channel pairs
// ---------------------------------------------------------------------------
__global__ void __launch_bounds__(256, 1)
conv_kernel(const float* __restrict__ x,
            const float* __restrict__ bias,
            float* __restrict__ out)
{
    extern __shared__ float smem[];
    float* ws = smem;                 // 2 x WS_BUF
    float* xs = smem + 2 * WS_BUF;    // 2 x XS_BUF

    const int tid = threadIdx.x;
    const int fl  = tid & 1;
    const int tg  = (tid >> 1) & 7;
    const int og  = tid >> 4;
    const int f0  = blockIdx.x * 2;
    const int t0  = blockIdx.y * TT;
    const int b   = blockIdx.z;
    const int f   = f0 + fl;
    const int tl  = tg * 8;
    const int ob  = og * 4;

    const uint32_t smem_base = (uint32_t)__cvta_generic_to_shared(smem);
    const float* xb = x + (size_t)b * CIN * TDIM * FDIM;

    // ---- accumulators init with bias: acc2[op][rt] = {out(ob+2op), out(ob+2op+1)} ----
    uint64_t acc2[2][8];
#pragma unroll
    for (int op = 0; op < 2; op++) {
        float b0 = (f < FDIM) ? bias[(ob + 2 * op) * FDIM + f] : 0.f;
        float b1 = (f < FDIM) ? bias[(ob + 2 * op + 1) * FDIM + f] : 0.f;
        uint64_t bb = pack2(b0, b1);
#pragma unroll
        for (int rt = 0; rt < 8; rt++) acc2[op][rt] = bb;
    }

    // ---- prefetch of one chunk (weights + x halo tile) into buffer buf ----
    auto prefetch = [&](int c, int buf) {
        const int i0 = c * IC;
        const uint32_t wdst0 = smem_base + (uint32_t)(buf * WS_BUF) * 4u;
#pragma unroll
        for (int j = 0; j < 12; j++) {
            int q   = j * 256 + tid;          // < 3072
            int blk = q / 192;                // i*2 + fl2
            int r   = q - blk * 192;          // float4 within block
            int ii  = blk >> 1;
            int fl2 = blk & 1;
            int ff  = min(f0 + fl2, FDIM - 1);
            const float* src = g_wT + (size_t)(ff * CIN + i0 + ii) * 768 + r * 4;
            uint32_t dst = wdst0 + (uint32_t)(blk * WS_BLK + r * 4) * 4u;
            cp_async16(dst, src);
        }
        const uint32_t xdst0 = smem_base + (uint32_t)(2 * WS_BUF + buf * XS_BUF) * 4u;
        for (int e = tid; e < IC * 66 * 4; e += 256) {
            int ff  = e & 3;
            int rem = e >> 2;                 // i*66 + tt
            int ii  = rem / 66;
            int tt  = rem - ii * 66;
            int gt  = t0 - 1 + tt;
            int gf  = f0 - 1 + ff;
            bool ok = (gt >= 0) & (gt < TDIM) & (gf >= 0) & (gf < FDIM);
            const float* src = xb + ((size_t)(i0 + ii) * TDIM + (ok ? gt : 0)) * FDIM
                                  + (ok ? gf : 0);
            uint32_t dst = xdst0 + (uint32_t)((ii * 4 + ff) * XS_ROW + tt) * 4u;
            cp_async4z(dst, src, ok);
        }
    };

    prefetch(0, 0);
    asm volatile("cp.async.commit_group;\n");

    for (int c = 0; c < NCH; c++) {
        if (c + 1 < NCH) {
            prefetch(c + 1, (c + 1) & 1);
            asm volatile("cp.async.commit_group;\n");
            asm volatile("cp.async.wait_group 1;\n");
        } else {
            asm volatile("cp.async.wait_group 0;\n");
        }
        __syncthreads();

        const float* wsb = ws + (c & 1) * WS_BUF;
        const float* xsb = xs + (c & 1) * XS_BUF;

#pragma unroll 1
        for (int i = 0; i < IC; i++) {
            // x window: 10 t-positions x 3 freq offsets, broadcast-packed {x,x}
            uint64_t xb2[10][3];
#pragma unroll
            for (int n = 0; n < 3; n++) {
                const float* row = xsb + (i * 4 + fl + n) * XS_ROW + tl;
                float4 a  = *reinterpret_cast<const float4*>(row);
                float4 b4 = *reinterpret_cast<const float4*>(row + 4);
                float2 c2 = *reinterpret_cast<const float2*>(row + 8);
                xb2[0][n] = pack2(a.x,  a.x);
                xb2[1][n] = pack2(a.y,  a.y);
                xb2[2][n] = pack2(a.z,  a.z);
                xb2[3][n] = pack2(a.w,  a.w);
                xb2[4][n] = pack2(b4.x, b4.x);
                xb2[5][n] = pack2(b4.y, b4.y);
                xb2[6][n] = pack2(b4.z, b4.z);
                xb2[7][n] = pack2(b4.w, b4.w);
                xb2[8][n] = pack2(c2.x, c2.x);
                xb2[9][n] = pack2(c2.y, c2.y);
            }
#pragma unroll
            for (int op = 0; op < 2; op++) {
                // weights for o = ob+2op (row A) and ob+2op+1 (row B), 12 apart
                const float* wrow = wsb + (i * 2 + fl) * WS_BLK + (ob + 2 * op) * 12;
                float4 a0 = *reinterpret_cast<const float4*>(wrow);
                float4 a1 = *reinterpret_cast<const float4*>(wrow + 4);
                float  a8 = wrow[8];
                float4 c0 = *reinterpret_cast<const float4*>(wrow + 12);
                float4 c1 = *reinterpret_cast<const float4*>(wrow + 16);
                float  c8 = wrow[20];
                uint64_t w2[9];
                w2[0] = pack2(a0.x, c0.x);
                w2[1] = pack2(a0.y, c0.y);
                w2[2] = pack2(a0.z, c0.z);
                w2[3] = pack2(a0.w, c0.w);
                w2[4] = pack2(a1.x, c1.x);
                w2[5] = pack2(a1.y, c1.y);
                w2[6] = pack2(a1.z, c1.z);
                w2[7] = pack2(a1.w, c1.w);
                w2[8] = pack2(a8,   c8);
#pragma unroll
                for (int rt = 0; rt < 8; rt++) {
                    uint64_t s = acc2[op][rt];
#pragma unroll
                    for (int m = 0; m < 3; m++)
#pragma unroll
                        for (int n = 0; n < 3; n++)
                            ffma2(s, w2[m * 3 + n], xb2[rt + m][n]);
                    acc2[op][rt] = s;
                }
            }
        }
        __syncthreads();
    }

    // ---- store (unpack channel pairs) ----
    if (f < FDIM) {
#pragma unroll
        for (int op = 0; op < 2; op++) {
            float* o0 = out + (((size_t)b * COUT + ob + 2 * op) * TDIM + (t0 + tl)) * FDIM + f;
            float* o1 = o0 + (size_t)TDIM * FDIM;
#pragma unroll
            for (int rt = 0; rt < 8; rt++) {
                float lo, hi;
                unpack2(lo, hi, acc2[op][rt]);
                o0[(size_t)rt * FDIM] = lo;
                o1[(size_t)rt * FDIM] = hi;
            }
        }
    }
}

// ---------------------------------------------------------------------------
// Launch
// ---------------------------------------------------------------------------
extern "C" void kernel_launch(void* const* d_in, const int* in_sizes, int n_in,
                              void* d_out, int out_size)
{
    const float* x    = (const float*)d_in[0];
    const float* w    = (const float*)d_in[1];
    const float* bias = (const float*)d_in[2];
    float* out        = (float*)d_out;

    cudaFuncSetAttribute(conv_kernel,
                         cudaFuncAttributeMaxDynamicSharedMemorySize,
                         SMEM_FLOATS * 4);

    int total = FDIM * CIN * COUT;
    wtrans_kernel<<<(total + 255) / 256, 256>>>(w);

    dim3 grid((FDIM + 1) / 2, TDIM / TT, CB);
    conv_kernel<<<grid, 256, SMEM_FLOATS * 4>>>(x, bias, out);
}

// round 6
// speedup vs baseline: 2.5046x; 2.5046x over previous
#include <cuda_runtime.h>
#include <cstdint>
#include <cstddef>

#define CB    8
#define CIN   64
#define COUT  64
#define TDIM  512
#define FDIM  161

constexpr int NFP   = 81;          // f-pairs
constexpr int NCHK  = 8;           // CIN chunks of 8
constexpr int TT    = 128;         // t-tile (GEMM N)
constexpr int NT    = TDIM / TT;   // 4
constexpr int NSTEP = 12;          // k8 steps per chunk (K_chunk = 96 = 8i * 12(m,n4))

// A tile per (fp,chunk): fragment-ordered [step][mtile][lane][4] tf32
constexpr int ATILE = NSTEP * 8 * 32 * 4;   // 12288 floats = 49152 B
constexpr int XTILE = 8 * 130 * 4;          // 4160 floats  = 16640 B  ([i][ts][n4])

constexpr int SM_A0 = 0;
constexpr int SM_A1 = 49152;
constexpr int SM_X0 = 98304;
constexpr int SM_X1 = SM_X0 + 16640;
constexpr int SM_TOTAL = SM_X1 + 16640;     // 131584 B

__device__ float g_wA[(size_t)NFP * NCHK * ATILE];   // 31.9 MB

// ---------------------------------------------------------------------------
__device__ __forceinline__ void cp_async16(uint32_t s, const void* g)
{
    asm volatile("cp.async.ca.shared.global [%0], [%1], 16;\n" :: "r"(s), "l"(g));
}
__device__ __forceinline__ void cp_async4z(uint32_t s, const void* g, bool ok)
{
    int sz = ok ? 4 : 0;
    asm volatile("cp.async.ca.shared.global [%0], [%1], 4, %2;\n" :: "r"(s), "l"(g), "r"(sz));
}
__device__ __forceinline__ uint32_t smem_u32(const void* p)
{
    uint32_t a;
    asm("{ .reg .u64 t; cvta.to.shared.u64 t, %1; cvt.u32.u64 %0, t; }" : "=r"(a) : "l"(p));
    return a;
}
__device__ __forceinline__ void mma_tf32(float& d0, float& d1, float& d2, float& d3,
                                         uint32_t a0, uint32_t a1, uint32_t a2, uint32_t a3,
                                         uint32_t b0, uint32_t b1)
{
    asm volatile("mma.sync.aligned.m16n8k8.row.col.f32.tf32.tf32.f32 "
                 "{%0,%1,%2,%3}, {%4,%5,%6,%7}, {%8,%9}, {%0,%1,%2,%3};"
                 : "+f"(d0), "+f"(d1), "+f"(d2), "+f"(d3)
                 : "r"(a0), "r"(a1), "r"(a2), "r"(a3), "r"(b0), "r"(b1));
}

// ---------------------------------------------------------------------------
// Weight transform: kernel[o][i][f][m][n] -> fragment-ordered A tiles.
// Per (fp,chunk): element at ((s*8+mt)*32+l)*4+r holds A[row][k] for
//   row = mt*16 + (l>>2) + 8*(r&1), k = s*8 + (l&3) + 4*(r>>1)
//   k -> i = ch*8 + k/12, m = (k%12)>>2, n4 = (k%12)&3; n = n4 - fh
// ---------------------------------------------------------------------------
__global__ void wtrans(const float* __restrict__ w)
{
    long idx = (long)blockIdx.x * 256 + threadIdx.x;
    const long total = (long)NFP * NCHK * ATILE;
    if (idx >= total) return;
    int e    = (int)(idx % ATILE);
    int tile = (int)(idx / ATILE);
    int ch = tile & 7;
    int fp = tile >> 3;
    int r  = e & 3;
    int l  = (e >> 2) & 31;
    int mt = (e >> 7) & 7;
    int s  = e >> 10;
    int row = mt * 16 + (l >> 2) + 8 * (r & 1);
    int k   = s * 8 + (l & 3) + 4 * (r >> 1);
    int i   = ch * 8 + k / 12;
    int rr  = k % 12;
    int m  = rr >> 2, n4 = rr & 3;
    int fh = row >> 6, o = row & 63;
    int f  = fp * 2 + fh;
    int n  = n4 - fh;
    float v = 0.f;
    if (n >= 0 && n < 3 && f < FDIM)
        v = w[(((size_t)(o * CIN + i) * FDIM + f) * 3 + m) * 3 + n];
    uint32_t tv; asm("cvt.rna.tf32.f32 %0, %1;" : "=r"(tv) : "f"(v));
    ((uint32_t*)g_wA)[idx] = tv;
}

// ---------------------------------------------------------------------------
// Main kernel: CTA = (fp, t-tile, b) -> out[b, 0:64, t0:t0+128, 2fp:2fp+2]
// 8 warps: warp_m = wid&3 (32 rows each), warp_n = wid>>2 (64 cols each)
// ---------------------------------------------------------------------------
__global__ void __launch_bounds__(256, 1)
conv_mma(const float* __restrict__ x,
         const float* __restrict__ bias,
         float* __restrict__ out)
{
    extern __shared__ __align__(16) char smem[];
    const uint32_t sbase = smem_u32(smem);
    const int tid    = threadIdx.x;
    const int wid    = tid >> 5;
    const int lane   = tid & 31;
    const int warp_m = wid & 3;
    const int warp_n = wid >> 2;
    const int fp     = blockIdx.x;
    const int t0     = blockIdx.y * TT;
    const int b      = blockIdx.z;
    const int fbase  = fp * 2;
    const float* xb  = x + (size_t)b * CIN * TDIM * FDIM;

    // ---- per-thread B-fragment base offsets (chunk-invariant) ----
    // B elem addr (floats) = P + t*4, P = i*520 + m*4 + n4 for k = s*8+(lane&3)(+4)
    int P0[NSTEP], P1[NSTEP];
#pragma unroll
    for (int s = 0; s < NSTEP; s++) {
        int k0 = s * 8 + (lane & 3), k1 = k0 + 4;
        int i0 = k0 / 12, r0 = k0 % 12;
        int i1 = k1 / 12, r1 = k1 % 12;
        P0[s] = i0 * 520 + (r0 >> 2) * 4 + (r0 & 3);
        P1[s] = i1 * 520 + (r1 >> 2) * 4 + (r1 & 3);
    }

    // ---- accumulators init with bias ----
    float D[2][8][4];
#pragma unroll
    for (int w2 = 0; w2 < 2; w2++) {
#pragma unroll
        for (int h = 0; h < 2; h++) {
            int row = warp_m * 32 + w2 * 16 + (lane >> 2) + 8 * h;
            int fh = row >> 6, o = row & 63;
            int f = fbase + fh;
            float bv = (f < FDIM) ? bias[o * FDIM + f] : 0.f;
#pragma unroll
            for (int nt = 0; nt < 8; nt++) {
                D[w2][nt][2 * h + 0] = bv;
                D[w2][nt][2 * h + 1] = bv;
            }
        }
    }

    // ---- chunk prefetch: A (pre-packed, 16B copies) + x halo tile ----
    auto prefetch = [&](int c, int buf) {
        const float4* asrc = (const float4*)(g_wA + (size_t)(fp * NCHK + c) * ATILE);
        uint32_t ad = sbase + (buf ? SM_A1 : SM_A0);
#pragma unroll
        for (int j = 0; j < 12; j++) {
            int q = j * 256 + tid;               // < 3072
            cp_async16(ad + q * 16, asrc + q);
        }
        const float* xc = xb + (size_t)c * 8 * TDIM * FDIM;
        uint32_t xd = sbase + (buf ? SM_X1 : SM_X0);
        for (int e = tid; e < XTILE; e += 256) {
            int n4  = e & 3;
            int rem = e >> 2;                    // i*130 + ts
            int i   = (int)(((unsigned)rem * 4033u) >> 19);   // rem/130
            int ts  = rem - i * 130;
            int gt  = t0 - 1 + ts;
            int gf  = fbase - 1 + n4;
            bool ok = (gt >= 0) & (gt < TDIM) & (gf >= 0) & (gf < FDIM);
            const float* src = xc + ((size_t)i * TDIM + (ok ? gt : 0)) * FDIM + (ok ? gf : 0);
            cp_async4z(xd + e * 4, src, ok);
        }
        asm volatile("cp.async.commit_group;\n");
    };

    prefetch(0, 0);

    for (int c = 0; c < NCHK; c++) {
        if (c + 1 < NCHK) {
            prefetch(c + 1, (c + 1) & 1);
            asm volatile("cp.async.wait_group 1;\n");
        } else {
            asm volatile("cp.async.wait_group 0;\n");
        }
        __syncthreads();

        const int buf = c & 1;
        const uint32_t* asb = (const uint32_t*)(smem + (buf ? SM_A1 : SM_A0));
        const uint32_t* xsb = (const uint32_t*)(smem + (buf ? SM_X1 : SM_X0));

#pragma unroll
        for (int s = 0; s < NSTEP; s++) {
            uint32_t a[2][4];
#pragma unroll
            for (int w2 = 0; w2 < 2; w2++) {
                const uint4* ap = (const uint4*)asb + ((s * 8 + warp_m * 2 + w2) * 32 + lane);
                uint4 av = *ap;
                a[w2][0] = av.x; a[w2][1] = av.y; a[w2][2] = av.z; a[w2][3] = av.w;
            }
            const int tB = warp_n * 64 + (lane >> 2);   // + nt*8
#pragma unroll
            for (int nt = 0; nt < 8; nt++) {
                int toff = (tB + nt * 8) * 4;
                uint32_t b0 = xsb[P0[s] + toff];
                uint32_t b1 = xsb[P1[s] + toff];
                mma_tf32(D[0][nt][0], D[0][nt][1], D[0][nt][2], D[0][nt][3],
                         a[0][0], a[0][1], a[0][2], a[0][3], b0, b1);
                mma_tf32(D[1][nt][0], D[1][nt][1], D[1][nt][2], D[1][nt][3],
                         a[1][0], a[1][1], a[1][2], a[1][3], b0, b1);
            }
        }
        __syncthreads();
    }

    // ---- epilogue: direct stores (row -> (fh,o), col -> t) ----
#pragma unroll
    for (int w2 = 0; w2 < 2; w2++) {
#pragma unroll
        for (int h = 0; h < 2; h++) {
            int row = warp_m * 32 + w2 * 16 + (lane >> 2) + 8 * h;
            int fh = row >> 6, o = row & 63;
            int f = fbase + fh;
            if (f < FDIM) {
                float* op = out + ((size_t)(b * COUT + o) * TDIM + t0 + warp_n * 64) * FDIM + f;
#pragma unroll
                for (int nt = 0; nt < 8; nt++) {
                    int tb = nt * 8 + (lane & 3) * 2;
                    op[(size_t)(tb    ) * FDIM] = D[w2][nt][2 * h + 0];
                    op[(size_t)(tb + 1) * FDIM] = D[w2][nt][2 * h + 1];
                }
            }
        }
    }
}

// ---------------------------------------------------------------------------
extern "C" void kernel_launch(void* const* d_in, const int* in_sizes, int n_in,
                              void* d_out, int out_size)
{
    const float* x    = (const float*)d_in[0];
    const float* w    = (const float*)d_in[1];
    const float* bias = (const float*)d_in[2];
    float* out        = (float*)d_out;

    cudaFuncSetAttribute(conv_mma, cudaFuncAttributeMaxDynamicSharedMemorySize, SM_TOTAL);

    const long total = (long)NFP * NCHK * ATILE;
    wtrans<<<(unsigned)((total + 255) / 256), 256>>>(w);

    dim3 grid(NFP, NT, CB);
    conv_mma<<<grid, 256, SM_TOTAL>>>(x, bias, out);
}